// round 2
// baseline (speedup 1.0000x reference)
#include <cuda_runtime.h>
#include <math.h>

// ---------------------------------------------------------------------------
// Problem constants
// ---------------------------------------------------------------------------
#define Bc  64
#define Dc  2048
#define Hc  4096
#define NSc 25
#define Mc  128              // batched rows: 64 fwd + 64 bwd
#define MH  (Mc * Hc)        // 524288
#define MD  (Mc * Dc)        // 262144

// ---------------------------------------------------------------------------
// Device-global scratch (allocation-free rule)
// ---------------------------------------------------------------------------
__device__ float g_posF[Bc * Dc];
__device__ float g_momF[Bc * Dc];
__device__ float g_posB[Bc * Dc];
__device__ float g_momB[Bc * Dc];
__device__ float g_sldF[Bc];
__device__ float g_sldB[Bc];
__device__ float g_Xa[MD];                 // net input a  (128 x 2048)
__device__ float g_Xb[MD];                 // net input b  (128 x 2048)
__device__ float g_P1[2 * MH];             // layer-1 partials (Xa@W1, Xb@W2)
__device__ float g_P2[2 * MH];             // layer-2 partials (two K-halves)
__device__ float g_P3[6 * MD];             // layer-3 partials: z = half*3 + {S,T,Q}
__device__ float g_bias1[2 * NSc * Hc];    // b1 + t@Wt per (net, step)

// ---------------------------------------------------------------------------
// Init: copy states, build layer-1 biases, build first net input (MOM step)
// ---------------------------------------------------------------------------
__global__ __launch_bounds__(256) void init_k(
    const float* __restrict__ position, const float* __restrict__ momf,
    const float* __restrict__ momb, const float* __restrict__ b1,
    const float* __restrict__ Wt, const float* __restrict__ ts)
{
    int idx = blockIdx.x * blockDim.x + threadIdx.x;
    if (idx < Bc * Dc) {
        float p = position[idx];
        g_posF[idx] = p; g_posB[idx] = p;
        g_momF[idx] = momf[idx]; g_momB[idx] = momb[idx];
    }
    if (idx < MD) {
        int r = idx / Dc, d = idx - r * Dc;
        float p = position[(r & 63) * Dc + d];
        g_Xa[idx] = p;
        g_Xb[idx] = sinf(p);
    }
    if (idx < 2 * NSc * Hc) {
        int h = idx % Hc;
        int s = (idx / Hc) % NSc;
        int n = idx / (Hc * NSc);
        g_bias1[idx] = b1[n * Hc + h]
                     + ts[s * 2 + 0] * Wt[(n * 2 + 0) * Hc + h]
                     + ts[s * 2 + 1] * Wt[(n * 2 + 1) * Hc + h];
    }
    if (idx < Bc) { g_sldF[idx] = 0.f; g_sldB[idx] = 0.f; }
}

// ---------------------------------------------------------------------------
// Tiled fp32 GEMM. BM=128 (all batch rows), BN=64, BK=16, 256 threads,
// per-thread 8x4 microtile. GID selects which stage (A source / activation /
// partial-output) — stage pointers are device globals, weights come as args.
//   GID 1: P1[z] = Xz @ Wz                    (z: 0=Xa@W1, 1=Xb@W2)    K=2048
//   GID 2: P2[z] = relu(P1.0+P1.1+bias1) @ Wh_half[z]                  K=2048
//   GID 3: P3[z] = relu(P2.0+P2.1+bh) @ {Ws,Wtr,Wq}_half   z=half*3+o  K=2048
// ---------------------------------------------------------------------------
struct BP { const float* p[6]; };

template<int GID>
__global__ __launch_bounds__(256) void gemm_k(BP bp, const float* biasArg,
                                              int n, int sF, int sB)
{
    const int z = blockIdx.z;
    const float* A;
    const float* A2 = nullptr;
    const float* bF = nullptr;
    const float* bB = nullptr;
    float* P;
    int k0, lda, N;
    if (GID == 1) {
        A = (z == 0) ? g_Xa : g_Xb;
        P = g_P1 + (size_t)z * MH; k0 = 0; lda = Dc; N = Hc;
    } else if (GID == 2) {
        A  = g_P1; A2 = g_P1 + MH;
        bF = g_bias1 + ((size_t)n * NSc + sF) * Hc;
        bB = g_bias1 + ((size_t)n * NSc + sB) * Hc;
        P = g_P2 + (size_t)z * MH; k0 = z * 2048; lda = Hc; N = Hc;
    } else {
        A  = g_P2; A2 = g_P2 + MH;
        bF = biasArg; bB = biasArg;
        P = g_P3 + (size_t)z * MD; k0 = (z / 3) * 2048; lda = Hc; N = Dc;
    }
    const float* __restrict__ Bm = bp.p[z];
    const int K = 2048;

    __shared__ float As[16][128];
    __shared__ float Bs[16][64];

    const int tid = threadIdx.x;
    const int tm  = tid >> 4;      // 0..15 -> rows tm*8..tm*8+7
    const int tn  = tid & 15;      // 0..15 -> cols tn*4..tn*4+3
    const int bn0 = blockIdx.x * 64;

    float acc[8][4];
#pragma unroll
    for (int i = 0; i < 8; i++)
#pragma unroll
        for (int j = 0; j < 4; j++) acc[i][j] = 0.f;

    for (int kt = 0; kt < K; kt += 16) {
        // --- load A tile (128x16), store transposed, fused activation ---
#pragma unroll
        for (int j = 0; j < 2; j++) {
            int v  = tid + j * 256;          // 0..511
            int m  = v >> 2;                 // 0..127
            int kc = (v & 3) << 2;           // 0,4,8,12
            size_t off = (size_t)m * lda + (size_t)(k0 + kt + kc);
            float4 av = *(const float4*)(A + off);
            float4 r;
            if (GID != 1) {
                float4 bv = *(const float4*)(A2 + off);
                const float* bb = ((m < 64) ? bF : bB) + (k0 + kt + kc);
                float4 cv = *(const float4*)bb;
                r.x = fmaxf(av.x + bv.x + cv.x, 0.f);
                r.y = fmaxf(av.y + bv.y + cv.y, 0.f);
                r.z = fmaxf(av.z + bv.z + cv.z, 0.f);
                r.w = fmaxf(av.w + bv.w + cv.w, 0.f);
            } else {
                r = av;
            }
            As[kc + 0][m] = r.x; As[kc + 1][m] = r.y;
            As[kc + 2][m] = r.z; As[kc + 3][m] = r.w;
        }
        // --- load B tile (16x64) ---
        {
            int k  = tid >> 4;
            int n4 = (tid & 15) << 2;
            *(float4*)&Bs[k][n4] =
                *(const float4*)(Bm + (size_t)(kt + k) * N + (bn0 + n4));
        }
        __syncthreads();

#pragma unroll
        for (int kk = 0; kk < 16; kk++) {
            float a[8], bb[4];
            *(float4*)&a[0] = *(const float4*)&As[kk][tm * 8];
            *(float4*)&a[4] = *(const float4*)&As[kk][tm * 8 + 4];
            *(float4*)&bb[0] = *(const float4*)&Bs[kk][tn * 4];
#pragma unroll
            for (int i = 0; i < 8; i++)
#pragma unroll
                for (int j = 0; j < 4; j++)
                    acc[i][j] = fmaf(a[i], bb[j], acc[i][j]);
        }
        __syncthreads();
    }

#pragma unroll
    for (int i = 0; i < 8; i++) {
        float4 o = make_float4(acc[i][0], acc[i][1], acc[i][2], acc[i][3]);
        *(float4*)(P + (size_t)(tm * 8 + i) * N + (bn0 + tn * 4)) = o;
    }
}

// ---------------------------------------------------------------------------
// Elementwise: S/T/Q epilogue + leapfrog update + logdet rowsum + next-input
// prep, one block per batch row (128 blocks). type: 1=MOM, 0=POS.
// ---------------------------------------------------------------------------
__global__ __launch_bounds__(256) void ep_k(
    int type, const float* __restrict__ eps,
    const float* __restrict__ bs, const float* __restrict__ cs,
    const float* __restrict__ btr, const float* __restrict__ bq,
    const float* __restrict__ cq,
    const float* cmF, int ciF, const float* cmB, int ciB,
    int nextType, const float* nmF, int niF, const float* nmB, int niB)
{
    const int r = blockIdx.x;
    const bool fwd = (r < 64);
    const int sr = fwd ? r : r - 64;
    float* pos = fwd ? g_posF : g_posB;
    float* mom = fwd ? g_momF : g_momB;
    const float* cm = fwd ? cmF : cmB;  const int ci = fwd ? ciF : ciB;
    const float* nm = fwd ? nmF : nmB;  const int ni = fwd ? niF : niB;
    const float e = eps[0];

    float lds = 0.f;
    for (int d = threadIdx.x; d < Dc; d += 256) {
        size_t ro = (size_t)r * Dc + d;
        size_t so = (size_t)sr * Dc + d;
        float Sv = tanhf(g_P3[0 * MD + ro] + g_P3[3 * MD + ro] + bs[d]) * expf(cs[d]);
        float Tv = g_P3[1 * MD + ro] + g_P3[4 * MD + ro] + btr[d];
        float Qv = tanhf(g_P3[2 * MD + ro] + g_P3[5 * MD + ro] + bq[d]) * expf(cq[d]);
        float etr = expf(e * Qv);

        float p = pos[so], v = mom[so];
        if (type == 1) {                       // momentum half-step
            float gg = sinf(p);
            float sc = (fwd ? 0.5f : -0.5f) * e * Sv;
            float es = expf(sc);
            v = fwd ? (v * es - 0.5f * e * (etr * gg - Tv))
                    : (es * (v + 0.5f * e * (etr * gg - Tv)));
            mom[so] = v;
            lds += sc;
        } else {                               // position step (masked)
            float mk = cm[d]; if (ci) mk = 1.f - mk;
            float mi = 1.f - mk;
            float sc = e * Sv;
            float es = expf(sc);
            p = fwd ? (mk * p + mi * (p * es + e * (etr * v + Tv)))
                    : (mk * p + mi * es * (p - e * (etr * v + Tv)));
            pos[so] = p;
            lds += mi * sc;
        }
        // prep next sub-step's net inputs
        if (nextType == 1) {
            g_Xa[ro] = p; g_Xb[ro] = sinf(p);
        } else {
            float k = nm[d]; if (ni) k = 1.f - k;
            g_Xa[ro] = v; g_Xb[ro] = k * p;
        }
    }
    __shared__ float red[256];
    red[threadIdx.x] = lds;
    __syncthreads();
    for (int s2 = 128; s2 > 0; s2 >>= 1) {
        if (threadIdx.x < s2) red[threadIdx.x] += red[threadIdx.x + s2];
        __syncthreads();
    }
    if (threadIdx.x == 0) {
        float* sld = fwd ? g_sldF : g_sldB;
        sld[sr] += red[0];
    }
}

// ---------------------------------------------------------------------------
// Final: hamiltonians, accept prob, output assembly. One block per batch row.
// Output layout: [pos_post (64x2048)][mom_post (64x2048)][ap (64)][pos_out]
// ---------------------------------------------------------------------------
__global__ __launch_bounds__(256) void final_k(
    const float* __restrict__ position, const float* __restrict__ momf0,
    const float* __restrict__ momb0, const float* __restrict__ u_dir,
    const float* __restrict__ u_accept, float* __restrict__ out)
{
    const int b = blockIdx.x;
    float acc7[7] = {0.f, 0.f, 0.f, 0.f, 0.f, 0.f, 0.f};
    for (int d = threadIdx.x; d < Dc; d += 256) {
        size_t o = (size_t)b * Dc + d;
        float x0 = position[o];  acc7[0] += 1.f - cosf(x0);
        float a  = momf0[o];     acc7[1] += 0.5f * a * a;
        float c  = momb0[o];     acc7[2] += 0.5f * c * c;
        float pf = g_posF[o];    acc7[3] += 1.f - cosf(pf);
        float mf = g_momF[o];    acc7[4] += 0.5f * mf * mf;
        float pb = g_posB[o];    acc7[5] += 1.f - cosf(pb);
        float mb = g_momB[o];    acc7[6] += 0.5f * mb * mb;
    }
    __shared__ float red[256];
    __shared__ float tot[7];
    for (int q = 0; q < 7; q++) {
        red[threadIdx.x] = acc7[q];
        __syncthreads();
        for (int s2 = 128; s2 > 0; s2 >>= 1) {
            if (threadIdx.x < s2) red[threadIdx.x] += red[threadIdx.x + s2];
            __syncthreads();
        }
        if (threadIdx.x == 0) tot[q] = red[0];
        __syncthreads();
    }
    __shared__ float s_fm, s_am;
    if (threadIdx.x == 0) {
        float df  = (tot[0] + tot[1]) - (tot[3] + tot[4]) + g_sldF[b];
        float apf = expf(fminf(df, 0.f)); if (!isfinite(apf)) apf = 0.f;
        float db  = (tot[0] + tot[2]) - (tot[5] + tot[6]) + g_sldB[b];
        float apb = expf(fminf(db, 0.f)); if (!isfinite(apb)) apb = 0.f;
        float fm  = (u_dir[b] > 0.5f) ? 1.f : 0.f;
        float ap  = fm * apf + (1.f - fm) * apb;
        out[2 * Bc * Dc + b] = ap;
        s_fm = fm;
        s_am = (ap > u_accept[b]) ? 1.f : 0.f;
    }
    __syncthreads();
    const float fm = s_fm, am = s_am;
    for (int d = threadIdx.x; d < Dc; d += 256) {
        size_t o = (size_t)b * Dc + d;
        float pp = fm * g_posF[o] + (1.f - fm) * g_posB[o];
        float mp = fm * g_momF[o] + (1.f - fm) * g_momB[o];
        out[o] = pp;
        out[(size_t)Bc * Dc + o] = mp;
        out[(size_t)2 * Bc * Dc + Bc + o] = am * pp + (1.f - am) * position[o];
    }
}

// ---------------------------------------------------------------------------
// Host driver
// ---------------------------------------------------------------------------
extern "C" void kernel_launch(void* const* d_in, const int* in_sizes, int n_in,
                              void* d_out, int out_size)
{
    const float* position = (const float*)d_in[0];
    const float* momf     = (const float*)d_in[1];
    const float* momb     = (const float*)d_in[2];
    const float* u_dir    = (const float*)d_in[3];
    const float* u_acc    = (const float*)d_in[4];
    const float* eps      = (const float*)d_in[5];
    const float* masks    = (const float*)d_in[6];
    const float* ts       = (const float*)d_in[7];
    const float* W1       = (const float*)d_in[8];
    const float* W2       = (const float*)d_in[9];
    const float* Wt       = (const float*)d_in[10];
    const float* b1       = (const float*)d_in[11];
    const float* Wh       = (const float*)d_in[12];
    const float* bh       = (const float*)d_in[13];
    const float* Ws       = (const float*)d_in[14];
    const float* bs       = (const float*)d_in[15];
    const float* cs       = (const float*)d_in[16];
    const float* Wtr      = (const float*)d_in[17];
    const float* btr      = (const float*)d_in[18];
    const float* Wq       = (const float*)d_in[19];
    const float* bq       = (const float*)d_in[20];
    const float* cq       = (const float*)d_in[21];
    float* out = (float*)d_out;

    init_k<<<1024, 256>>>(position, momf, momb, b1, Wt, ts);

    const float* sel[3] = {Ws, Wtr, Wq};

    for (int step = 0; step < NSc; step++) {
        const int sF = step, sB = NSc - 1 - step;
        const float* mF = masks + (size_t)sF * Dc;
        const float* mB = masks + (size_t)sB * Dc;

        for (int sub = 0; sub < 4; sub++) {
            const int n = (sub == 0 || sub == 3) ? 1 : 0;  // MOM=1, POS=0

            // GEMM 1: two K=2048 segments (Xa@W1[n], Xb@W2[n])
            BP b1p;
            b1p.p[0] = W1 + (size_t)n * Dc * Hc;
            b1p.p[1] = W2 + (size_t)n * Dc * Hc;
            gemm_k<1><<<dim3(Hc / 64, 1, 2), 256>>>(b1p, nullptr, n, sF, sB);

            // GEMM 2: relu(P1+bias1) @ Wh[n], split-K into 2 halves
            BP b2p;
            b2p.p[0] = Wh + (size_t)n * Hc * Hc;
            b2p.p[1] = Wh + (size_t)n * Hc * Hc + (size_t)2048 * Hc;
            gemm_k<2><<<dim3(Hc / 64, 1, 2), 256>>>(b2p, nullptr, n, sF, sB);

            // GEMM 3: relu(P2+bh) @ {Ws,Wtr,Wq}[n], 3 outputs x 2 K-halves
            BP b3p;
            for (int zz = 0; zz < 6; zz++) {
                int o = zz % 3, half = zz / 3;
                b3p.p[zz] = sel[o] + (size_t)n * Hc * Dc + (size_t)half * 2048 * Dc;
            }
            gemm_k<3><<<dim3(Dc / 64, 1, 6), 256>>>(b3p, bh + (size_t)n * Hc,
                                                    n, sF, sB);

            // Elementwise update + next-input prep
            int type, nextType;
            const float *cmF = nullptr, *cmB = nullptr, *nmF = nullptr, *nmB = nullptr;
            int ciF = 0, ciB = 0, niF = 0, niB = 0;
            if (sub == 0) {        // MOM; next POS (fwd: m, bwd: 1-m)
                type = 1; nextType = 0;
                nmF = mF; niF = 0; nmB = mB; niB = 1;
            } else if (sub == 1) { // POS (fwd m / bwd 1-m); next POS swapped
                type = 0; nextType = 0;
                cmF = mF; ciF = 0; cmB = mB; ciB = 1;
                nmF = mF; niF = 1; nmB = mB; niB = 0;
            } else if (sub == 2) { // POS (fwd 1-m / bwd m); next MOM
                type = 0; nextType = 1;
                cmF = mF; ciF = 1; cmB = mB; ciB = 0;
            } else {               // MOM; next MOM (next step's sub0)
                type = 1; nextType = 1;
            }
            ep_k<<<128, 256>>>(type, eps,
                               bs + (size_t)n * Dc, cs + (size_t)n * Dc,
                               btr + (size_t)n * Dc, bq + (size_t)n * Dc,
                               cq + (size_t)n * Dc,
                               cmF, ciF, cmB, ciB,
                               nextType, nmF, niF, nmB, niB);
        }
    }

    final_k<<<64, 256>>>(position, momf, momb, u_dir, u_acc, out);
}

// round 4
// speedup vs baseline: 4.8631x; 4.8631x over previous
#include <cuda_runtime.h>
#include <cuda_bf16.h>
#include <math.h>
#include <stdint.h>

#define Bc  64
#define Dc  2048
#define Hc  4096
#define NSc 25
#define STR12 (128 * 4096)
#define SZ3   (128 * 6144)
#define PLANE_A 524288            // bf16 elems per A plane (128 x 4096)

// Weight image: per net n: [W12 | Wh | W3] each as [N][4096] bf16, hi plane then lo.
#define NET_STRIDE 117440512ULL   // (4096+4096+6144)*4096*2
#define R1OFF 0ULL
#define R2OFF 33554432ULL
#define R3OFF 67108864ULL

__device__ __nv_bfloat16 g_Wimg[234881024];   // 470MB
__device__ __nv_bfloat16 g_A1img[2 * PLANE_A];
__device__ __nv_bfloat16 g_A2img[2 * PLANE_A];
__device__ __nv_bfloat16 g_A3img[2 * PLANE_A];
__device__ float g_P1[4 * STR12];
__device__ float g_P2[4 * STR12];
__device__ float g_P3[4 * SZ3];
__device__ float g_posF[Bc * Dc];
__device__ float g_momF[Bc * Dc];
__device__ float g_posB[Bc * Dc];
__device__ float g_momB[Bc * Dc];
__device__ float g_sldF[Bc];
__device__ float g_sldB[Bc];
__device__ float g_bias1[2 * NSc * Hc];

// ---------------- helpers ----------------
__device__ __forceinline__ uint32_t smem_u32(const void* p) {
    uint32_t a;
    asm("{ .reg .u64 t; cvta.to.shared.u64 t, %1; cvt.u32.u64 %0, t; }" : "=r"(a) : "l"(p));
    return a;
}
#define LDSM4(r, a) \
    asm volatile("ldmatrix.sync.aligned.m8n8.x4.shared.b16 {%0,%1,%2,%3}, [%4];" \
        : "=r"((r)[0]), "=r"((r)[1]), "=r"((r)[2]), "=r"((r)[3]) : "r"(a))

__device__ __forceinline__ void mma16816(float* c, const uint32_t* a, const uint32_t* b) {
    asm volatile("mma.sync.aligned.m16n8k16.row.col.f32.bf16.bf16.f32 "
        "{%0,%1,%2,%3},{%4,%5,%6,%7},{%8,%9},{%0,%1,%2,%3};"
        : "+f"(c[0]), "+f"(c[1]), "+f"(c[2]), "+f"(c[3])
        : "r"(a[0]), "r"(a[1]), "r"(a[2]), "r"(a[3]), "r"(b[0]), "r"(b[1]));
}

__device__ __forceinline__ void split8(const float* v, uint4& h4, uint4& l4) {
    uint32_t h[4], l[4];
#pragma unroll
    for (int i = 0; i < 4; i++) {
        __nv_bfloat16 a = __float2bfloat16(v[2*i]), b = __float2bfloat16(v[2*i+1]);
        __nv_bfloat16 ra = __float2bfloat16(v[2*i]   - __bfloat162float(a));
        __nv_bfloat16 rb = __float2bfloat16(v[2*i+1] - __bfloat162float(b));
        h[i] = (uint32_t)__bfloat16_as_ushort(a)  | ((uint32_t)__bfloat16_as_ushort(b)  << 16);
        l[i] = (uint32_t)__bfloat16_as_ushort(ra) | ((uint32_t)__bfloat16_as_ushort(rb) << 16);
    }
    h4 = make_uint4(h[0], h[1], h[2], h[3]);
    l4 = make_uint4(l[0], l[1], l[2], l[3]);
}
__device__ __forceinline__ void plane_w8(__nv_bfloat16* img, int m, int k, const float* v) {
    uint4 h4, l4;
    split8(v, h4, l4);
    *(uint4*)(img + (size_t)m * 4096 + k) = h4;
    *(uint4*)(img + PLANE_A + (size_t)m * 4096 + k) = l4;
}

// ---------------- init ----------------
__global__ __launch_bounds__(256) void init_k(
    const float* __restrict__ position, const float* __restrict__ momf,
    const float* __restrict__ momb, const float* __restrict__ b1,
    const float* __restrict__ Wt, const float* __restrict__ ts)
{
    int idx = blockIdx.x * 256 + threadIdx.x;
    if (idx < Bc * Dc) {
        float p = position[idx];
        g_posF[idx] = p; g_posB[idx] = p;
        g_momF[idx] = momf[idx]; g_momB[idx] = momb[idx];
    }
    if (idx < 2 * NSc * Hc) {
        int h = idx % Hc, s = (idx / Hc) % NSc, n = idx / (Hc * NSc);
        g_bias1[idx] = b1[n * Hc + h]
                     + ts[s * 2 + 0] * Wt[(n * 2 + 0) * Hc + h]
                     + ts[s * 2 + 1] * Wt[(n * 2 + 1) * Hc + h];
    }
    if (idx < Bc) { g_sldF[idx] = 0.f; g_sldB[idx] = 0.f; }
}

__global__ __launch_bounds__(256) void initA_k(const float* __restrict__ position)
{
    int r = blockIdx.x, d0 = threadIdx.x * 8;
    const float* src = position + (size_t)(r & 63) * Dc + d0;
    float xa[8], xb[8];
#pragma unroll
    for (int c = 0; c < 8; c++) { float p = src[c]; xa[c] = p; xb[c] = sinf(p); }
    plane_w8(g_A1img, r, d0, xa);
    plane_w8(g_A1img, r, 2048 + d0, xb);
}

// ---------------- weight transpose + split: [k][n] fp32 -> [n][k] bf16 hi/lo
// grid (NTOT/128, 64). gtype 1: K-concat [W1;W2]. gtype 2: Wh. gtype 3: Ws|Wtr|Wq.
__global__ __launch_bounds__(256) void tw_k(
    const float* __restrict__ S0, const float* __restrict__ S1,
    const float* __restrict__ S2, int gtype, int NSRC, int NTOT,
    __nv_bfloat16* __restrict__ dst)
{
    __shared__ float sm[64 * 129];
    const int j = blockIdx.x, kb = blockIdx.y, tid = threadIdx.x;
    int n0 = (gtype == 3) ? (j & 15) * 128 : j * 128;
#pragma unroll
    for (int p = 0; p < 8; p++) {
        int kk = p * 8 + (tid >> 5), nn = (tid & 31) * 4;
        int kg = kb * 64 + kk;
        const float* sp;
        if (gtype == 1)      sp = (kg < 2048) ? S0 + (size_t)kg * NSRC : S1 + (size_t)(kg - 2048) * NSRC;
        else if (gtype == 2) sp = S0 + (size_t)kg * NSRC;
        else { const float* W = (j < 16) ? S0 : ((j < 32) ? S1 : S2); sp = W + (size_t)kg * NSRC; }
        float4 vv = *(const float4*)(sp + n0 + nn);
        sm[kk * 129 + nn + 0] = vv.x; sm[kk * 129 + nn + 1] = vv.y;
        sm[kk * 129 + nn + 2] = vv.z; sm[kk * 129 + nn + 3] = vv.w;
    }
    __syncthreads();
    size_t planeStride = (size_t)NTOT * 4096;
    int nbase = j * 128;
#pragma unroll
    for (int p = 0; p < 4; p++) {
        int pi = tid + p * 256;
        int rr = pi >> 3, u = pi & 7;
        float v[8];
#pragma unroll
        for (int c = 0; c < 8; c++) v[c] = sm[(u * 8 + c) * 129 + rr];
        uint4 h4, l4;
        split8(v, h4, l4);
        size_t off = (size_t)(nbase + rr) * 4096 + kb * 64 + u * 8;
        *(uint4*)(dst + off) = h4;
        *(uint4*)(dst + planeStride + off) = l4;
    }
}

// ---------------- HMMA GEMM: C[128 x 128] tile, split-K over blockIdx.z -----
// A planes: Ahi[128][4096], Alo at +PLANE_A. W planes: [NTOT][4096] hi, lo at +NTOT*4096.
__device__ __forceinline__ void ld_chunk(char* sbase, int tid,
    const __nv_bfloat16* Ahi, const __nv_bfloat16* Alo,
    const __nv_bfloat16* Whi, const __nv_bfloat16* Wlo, int kb)
{
#pragma unroll
    for (int j = 0; j < 16; j++) {
        int v = j * 256 + tid;
        int p = v >> 10, w = v & 1023;
        int r = w >> 3, c = w & 7;
        const __nv_bfloat16* src =
            (p == 0) ? Ahi + (size_t)r * 4096 + kb + c * 8 :
            (p == 1) ? Alo + (size_t)r * 4096 + kb + c * 8 :
            (p == 2) ? Whi + (size_t)r * 4096 + kb + c * 8 :
                       Wlo + (size_t)r * 4096 + kb + c * 8;
        uint32_t dst = smem_u32(sbase + p * 16384 + r * 128 + ((c ^ (r & 7)) << 4));
        asm volatile("cp.async.cg.shared.global [%0], [%1], 16;" :: "r"(dst), "l"(src));
    }
    asm volatile("cp.async.commit_group;" ::: "memory");
}

__global__ __launch_bounds__(256) void mma_gemm_k(
    const __nv_bfloat16* __restrict__ Aimg, const __nv_bfloat16* __restrict__ W,
    float* __restrict__ Pout, int NTOT, int NCH)
{
    extern __shared__ __align__(16) char smem[];
    const int tid = threadIdx.x, wid = tid >> 5, lane = tid & 31;
    const int ntile = blockIdx.x, z = blockIdx.z;
    const int kbase0 = z * NCH * 64;
    const int n0 = ntile * 128;
    const int wm = (wid >> 2) * 64;
    const int wn = (wid & 3) * 32;

    const __nv_bfloat16* Ahi = Aimg;
    const __nv_bfloat16* Alo = Aimg + PLANE_A;
    const __nv_bfloat16* Whi = W + (size_t)n0 * 4096;
    const __nv_bfloat16* Wlo = W + (size_t)NTOT * 4096 + (size_t)n0 * 4096;

    float acc[4][4][4];
#pragma unroll
    for (int f = 0; f < 4; f++)
#pragma unroll
        for (int g = 0; g < 4; g++)
#pragma unroll
            for (int q = 0; q < 4; q++) acc[f][g][q] = 0.f;

    ld_chunk(smem, tid, Ahi, Alo, Whi, Wlo, kbase0);

    const int sub = lane >> 3;
    const int arow = wm + (lane & 7) + ((sub & 1) ? 8 : 0);
    const int brow = wn + (lane & 7) + ((sub >> 1) ? 8 : 0);

    for (int i = 0; i < NCH; i++) {
        if (i + 1 < NCH) {
            ld_chunk(smem + ((i + 1) & 1) * 65536, tid, Ahi, Alo, Whi, Wlo,
                     kbase0 + (i + 1) * 64);
            asm volatile("cp.async.wait_group 1;" ::: "memory");
        } else {
            asm volatile("cp.async.wait_group 0;" ::: "memory");
        }
        __syncthreads();

        char* sb = smem + (i & 1) * 65536;
        uint32_t sA = smem_u32(sb);
        uint32_t sB = sA + 32768;
#pragma unroll
        for (int ks = 0; ks < 4; ks++) {
            uint32_t ahi[4][4], alo[4][4], bhi[4][2], blo[4][2];
            int akc = ks * 2 + (sub >> 1);
            int bkc = ks * 2 + (sub & 1);
#pragma unroll
            for (int f = 0; f < 4; f++) {
                int row = arow + f * 16;
                uint32_t ad = sA + row * 128 + ((akc ^ (row & 7)) << 4);
                LDSM4(ahi[f], ad);
                LDSM4(alo[f], ad + 16384);
            }
#pragma unroll
            for (int g = 0; g < 2; g++) {
                int row = brow + g * 16;
                uint32_t bd = sB + row * 128 + ((bkc ^ (row & 7)) << 4);
                uint32_t t[4];
                LDSM4(t, bd);
                bhi[g*2][0] = t[0]; bhi[g*2][1] = t[1];
                bhi[g*2+1][0] = t[2]; bhi[g*2+1][1] = t[3];
                LDSM4(t, bd + 16384);
                blo[g*2][0] = t[0]; blo[g*2][1] = t[1];
                blo[g*2+1][0] = t[2]; blo[g*2+1][1] = t[3];
            }
#pragma unroll
            for (int f = 0; f < 4; f++)
#pragma unroll
                for (int g = 0; g < 4; g++) {
                    mma16816(acc[f][g], ahi[f], bhi[g]);
                    mma16816(acc[f][g], ahi[f], blo[g]);
                    mma16816(acc[f][g], alo[f], bhi[g]);
                }
        }
        __syncthreads();
    }

    float* P = Pout + (size_t)z * 128 * NTOT;
    int mrow = wm + (lane >> 2);
    int ncol0 = n0 + wn + (lane & 3) * 2;
#pragma unroll
    for (int f = 0; f < 4; f++)
#pragma unroll
        for (int g = 0; g < 4; g++) {
            size_t o0 = (size_t)(mrow + f * 16) * NTOT + ncol0 + g * 8;
            *(float2*)(P + o0) = make_float2(acc[f][g][0], acc[f][g][1]);
            *(float2*)(P + o0 + 8 * NTOT) = make_float2(acc[f][g][2], acc[f][g][3]);
        }
}

// ---------------- activation: sum 4 split-K partials + bias + relu ----------
__global__ __launch_bounds__(256) void act_k(
    const float* __restrict__ P,
    const float* __restrict__ biasF, const float* __restrict__ biasB,
    __nv_bfloat16* __restrict__ outImg)
{
    int idx = blockIdx.x * 256 + threadIdx.x;
    int m = idx >> 9, k0 = (idx & 511) * 8;
    const float* row = P + (size_t)m * 4096 + k0;
    float v[8];
#pragma unroll
    for (int c = 0; c < 8; c++)
        v[c] = row[c] + row[STR12 + c] + row[2 * STR12 + c] + row[3 * STR12 + c];
    const float* bias = (m < 64) ? biasF : biasB;
#pragma unroll
    for (int c = 0; c < 8; c++) v[c] = fmaxf(v[c] + bias[k0 + c], 0.f);
    plane_w8(outImg, m, k0, v);
}

// ---------------- leapfrog elementwise + next-input planes ----------------
__global__ __launch_bounds__(256) void ep_k(
    int type, const float* __restrict__ eps,
    const float* __restrict__ bs, const float* __restrict__ cs,
    const float* __restrict__ btr, const float* __restrict__ bq,
    const float* __restrict__ cq,
    const float* cmF, int ciF, const float* cmB, int ciB,
    int nextType, const float* nmF, int niF, const float* nmB, int niB)
{
    const int r = blockIdx.x;
    const bool fwd = (r < 64);
    const int sr = fwd ? r : r - 64;
    float* pos = fwd ? g_posF : g_posB;
    float* mom = fwd ? g_momF : g_momB;
    const float* cm = fwd ? cmF : cmB;  const int ci = fwd ? ciF : ciB;
    const float* nm = fwd ? nmF : nmB;  const int ni = fwd ? niF : niB;
    const float e = eps[0];
    const int d0 = threadIdx.x * 8;

    float xa[8], xb[8], lds = 0.f;
#pragma unroll
    for (int c = 0; c < 8; c++) {
        int d = d0 + c;
        size_t ro = (size_t)r * 6144 + d;
        size_t so = (size_t)sr * Dc + d;
        float s0 = g_P3[ro] + g_P3[SZ3 + ro] + g_P3[2 * SZ3 + ro] + g_P3[3 * SZ3 + ro];
        float t0 = g_P3[ro + 2048] + g_P3[SZ3 + ro + 2048] + g_P3[2 * SZ3 + ro + 2048] + g_P3[3 * SZ3 + ro + 2048];
        float q0 = g_P3[ro + 4096] + g_P3[SZ3 + ro + 4096] + g_P3[2 * SZ3 + ro + 4096] + g_P3[3 * SZ3 + ro + 4096];
        float Sv = tanhf(s0 + bs[d]) * expf(cs[d]);
        float Tv = t0 + btr[d];
        float Qv = tanhf(q0 + bq[d]) * expf(cq[d]);
        float etr = expf(e * Qv);
        float p = pos[so], v = mom[so];
        if (type == 1) {
            float gg = sinf(p);
            float sc = (fwd ? 0.5f : -0.5f) * e * Sv;
            float es = expf(sc);
            v = fwd ? (v * es - 0.5f * e * (etr * gg - Tv))
                    : (es * (v + 0.5f * e * (etr * gg - Tv)));
            mom[so] = v;
            lds += sc;
        } else {
            float mk = cm[d]; if (ci) mk = 1.f - mk;
            float mi = 1.f - mk;
            float sc = e * Sv;
            float es = expf(sc);
            p = fwd ? (mk * p + mi * (p * es + e * (etr * v + Tv)))
                    : (mk * p + mi * es * (p - e * (etr * v + Tv)));
            pos[so] = p;
            lds += mi * sc;
        }
        if (nextType == 1) { xa[c] = p; xb[c] = sinf(p); }
        else { float k = nm[d]; if (ni) k = 1.f - k; xa[c] = v; xb[c] = k * p; }
    }
    plane_w8(g_A1img, r, d0, xa);
    plane_w8(g_A1img, r, 2048 + d0, xb);

    __shared__ float red[256];
    red[threadIdx.x] = lds;
    __syncthreads();
    for (int s2 = 128; s2 > 0; s2 >>= 1) {
        if (threadIdx.x < s2) red[threadIdx.x] += red[threadIdx.x + s2];
        __syncthreads();
    }
    if (threadIdx.x == 0) { (fwd ? g_sldF : g_sldB)[sr] += red[0]; }
}

// ---------------- final assembly ----------------
__global__ __launch_bounds__(256) void final_k(
    const float* __restrict__ position, const float* __restrict__ momf0,
    const float* __restrict__ momb0, const float* __restrict__ u_dir,
    const float* __restrict__ u_accept, float* __restrict__ out)
{
    const int b = blockIdx.x;
    float a7[7] = {0,0,0,0,0,0,0};
    for (int d = threadIdx.x; d < Dc; d += 256) {
        size_t o = (size_t)b * Dc + d;
        float x0 = position[o];  a7[0] += 1.f - cosf(x0);
        float a  = momf0[o];     a7[1] += 0.5f * a * a;
        float c  = momb0[o];     a7[2] += 0.5f * c * c;
        float pf = g_posF[o];    a7[3] += 1.f - cosf(pf);
        float mf = g_momF[o];    a7[4] += 0.5f * mf * mf;
        float pb = g_posB[o];    a7[5] += 1.f - cosf(pb);
        float mb = g_momB[o];    a7[6] += 0.5f * mb * mb;
    }
    __shared__ float red[256];
    __shared__ float tot[7];
    for (int q = 0; q < 7; q++) {
        red[threadIdx.x] = a7[q];
        __syncthreads();
        for (int s2 = 128; s2 > 0; s2 >>= 1) {
            if (threadIdx.x < s2) red[threadIdx.x] += red[threadIdx.x + s2];
            __syncthreads();
        }
        if (threadIdx.x == 0) tot[q] = red[0];
        __syncthreads();
    }
    __shared__ float s_fm, s_am;
    if (threadIdx.x == 0) {
        float df  = (tot[0] + tot[1]) - (tot[3] + tot[4]) + g_sldF[b];
        float apf = expf(fminf(df, 0.f)); if (!isfinite(apf)) apf = 0.f;
        float db  = (tot[0] + tot[2]) - (tot[5] + tot[6]) + g_sldB[b];
        float apb = expf(fminf(db, 0.f)); if (!isfinite(apb)) apb = 0.f;
        float fm  = (u_dir[b] > 0.5f) ? 1.f : 0.f;
        float ap  = fm * apf + (1.f - fm) * apb;
        out[2 * Bc * Dc + b] = ap;
        s_fm = fm;
        s_am = (ap > u_accept[b]) ? 1.f : 0.f;
    }
    __syncthreads();
    const float fm = s_fm, am = s_am;
    for (int d = threadIdx.x; d < Dc; d += 256) {
        size_t o = (size_t)b * Dc + d;
        float pp = fm * g_posF[o] + (1.f - fm) * g_posB[o];
        float mp = fm * g_momF[o] + (1.f - fm) * g_momB[o];
        out[o] = pp;
        out[(size_t)Bc * Dc + o] = mp;
        out[(size_t)2 * Bc * Dc + Bc + o] = am * pp + (1.f - am) * position[o];
    }
}

// ---------------- host driver ----------------
extern "C" void kernel_launch(void* const* d_in, const int* in_sizes, int n_in,
                              void* d_out, int out_size)
{
    const float* position = (const float*)d_in[0];
    const float* momf     = (const float*)d_in[1];
    const float* momb     = (const float*)d_in[2];
    const float* u_dir    = (const float*)d_in[3];
    const float* u_acc    = (const float*)d_in[4];
    const float* eps      = (const float*)d_in[5];
    const float* masks    = (const float*)d_in[6];
    const float* ts       = (const float*)d_in[7];
    const float* W1       = (const float*)d_in[8];
    const float* W2       = (const float*)d_in[9];
    const float* Wt       = (const float*)d_in[10];
    const float* b1       = (const float*)d_in[11];
    const float* Wh       = (const float*)d_in[12];
    const float* bh       = (const float*)d_in[13];
    const float* Ws       = (const float*)d_in[14];
    const float* bs       = (const float*)d_in[15];
    const float* cs       = (const float*)d_in[16];
    const float* Wtr      = (const float*)d_in[17];
    const float* btr      = (const float*)d_in[18];
    const float* Wq       = (const float*)d_in[19];
    const float* bq       = (const float*)d_in[20];
    const float* cq       = (const float*)d_in[21];
    float* out = (float*)d_out;

    const int DSM = 131072;
    cudaFuncSetAttribute(mma_gemm_k, cudaFuncAttributeMaxDynamicSharedMemorySize, DSM);

    void *pW, *pA1, *pA2, *pA3, *pP1, *pP2, *pP3, *pBias;
    cudaGetSymbolAddress(&pW,  g_Wimg);
    cudaGetSymbolAddress(&pA1, g_A1img);
    cudaGetSymbolAddress(&pA2, g_A2img);
    cudaGetSymbolAddress(&pA3, g_A3img);
    cudaGetSymbolAddress(&pP1, g_P1);
    cudaGetSymbolAddress(&pP2, g_P2);
    cudaGetSymbolAddress(&pP3, g_P3);
    cudaGetSymbolAddress(&pBias, g_bias1);
    __nv_bfloat16* Wimg = (__nv_bfloat16*)pW;
    const float* bias1d = (const float*)pBias;

    init_k<<<800, 256>>>(position, momf, momb, b1, Wt, ts);
    initA_k<<<128, 256>>>(position);
    for (int n = 0; n < 2; n++) {
        __nv_bfloat16* base = Wimg + (size_t)n * NET_STRIDE;
        tw_k<<<dim3(32, 64), 256>>>(W1 + (size_t)n * Dc * Hc, W2 + (size_t)n * Dc * Hc,
                                    nullptr, 1, Hc, 4096, base + R1OFF);
        tw_k<<<dim3(32, 64), 256>>>(Wh + (size_t)n * Hc * Hc, nullptr,
                                    nullptr, 2, Hc, 4096, base + R2OFF);
        tw_k<<<dim3(48, 64), 256>>>(Ws + (size_t)n * Hc * Dc, Wtr + (size_t)n * Hc * Dc,
                                    Wq + (size_t)n * Hc * Dc, 3, Dc, 6144, base + R3OFF);
    }

    for (int step = 0; step < NSc; step++) {
        const int sF = step, sB = NSc - 1 - step;
        const float* mF = masks + (size_t)sF * Dc;
        const float* mB = masks + (size_t)sB * Dc;

        for (int sub = 0; sub < 4; sub++) {
            const int n = (sub == 0 || sub == 3) ? 1 : 0;   // MOM=1, POS=0
            __nv_bfloat16* base = Wimg + (size_t)n * NET_STRIDE;

            mma_gemm_k<<<dim3(32, 1, 4), 256, DSM>>>(
                (const __nv_bfloat16*)pA1, base + R1OFF, (float*)pP1, 4096, 16);
            act_k<<<256, 256>>>((const float*)pP1,
                                bias1d + ((size_t)n * NSc + sF) * Hc,
                                bias1d + ((size_t)n * NSc + sB) * Hc,
                                (__nv_bfloat16*)pA2);
            mma_gemm_k<<<dim3(32, 1, 4), 256, DSM>>>(
                (const __nv_bfloat16*)pA2, base + R2OFF, (float*)pP2, 4096, 16);
            act_k<<<256, 256>>>((const float*)pP2,
                                bh + (size_t)n * Hc, bh + (size_t)n * Hc,
                                (__nv_bfloat16*)pA3);
            mma_gemm_k<<<dim3(48, 1, 4), 256, DSM>>>(
                (const __nv_bfloat16*)pA3, base + R3OFF, (float*)pP3, 6144, 16);

            int type, nextType;
            const float *cmF = nullptr, *cmB = nullptr, *nmF = nullptr, *nmB = nullptr;
            int ciF = 0, ciB = 0, niF = 0, niB = 0;
            if (sub == 0) {
                type = 1; nextType = 0; nmF = mF; niF = 0; nmB = mB; niB = 1;
            } else if (sub == 1) {
                type = 0; nextType = 0;
                cmF = mF; ciF = 0; cmB = mB; ciB = 1;
                nmF = mF; niF = 1; nmB = mB; niB = 0;
            } else if (sub == 2) {
                type = 0; nextType = 1; cmF = mF; ciF = 1; cmB = mB; ciB = 0;
            } else {
                type = 1; nextType = 1;
            }
            ep_k<<<128, 256>>>(type, eps,
                               bs + (size_t)n * Dc, cs + (size_t)n * Dc,
                               btr + (size_t)n * Dc, bq + (size_t)n * Dc,
                               cq + (size_t)n * Dc,
                               cmF, ciF, cmB, ciB,
                               nextType, nmF, niF, nmB, niB);
        }
    }

    final_k<<<64, 256>>>(position, momf, momb, u_dir, u_acc, out);
}

// round 5
// speedup vs baseline: 5.8451x; 1.2019x over previous
#include <cuda_runtime.h>
#include <cuda_bf16.h>
#include <math.h>
#include <stdint.h>

#define Bc  64
#define Dc  2048
#define Hc  4096
#define NSc 25
#define STR12 (128 * 4096)
#define SZ3   (128 * 6144)
#define PLANE_A 524288            // bf16 elems per A plane (128 x 4096)

// Weight image: per net n: [W12 | Wh | W3] each as [N][4096] bf16, hi plane then lo.
#define NET_STRIDE 117440512ULL   // (4096+4096+6144)*4096*2
#define R1OFF 0ULL
#define R2OFF 33554432ULL
#define R3OFF 67108864ULL

__device__ __nv_bfloat16 g_Wimg[234881024];   // 470MB
__device__ __nv_bfloat16 g_A1img[2 * PLANE_A];
__device__ __nv_bfloat16 g_A2img[2 * PLANE_A];
__device__ __nv_bfloat16 g_A3img[2 * PLANE_A];
__device__ float g_P1[4 * STR12];
__device__ float g_P2[4 * STR12];
__device__ float g_P3[3 * SZ3];
__device__ float g_posF[Bc * Dc];
__device__ float g_momF[Bc * Dc];
__device__ float g_posB[Bc * Dc];
__device__ float g_momB[Bc * Dc];
__device__ float g_sldF[Bc];
__device__ float g_sldB[Bc];
__device__ float g_bias1[2 * NSc * Hc];

// ---------------- helpers ----------------
__device__ __forceinline__ uint32_t smem_u32(const void* p) {
    uint32_t a;
    asm("{ .reg .u64 t; cvta.to.shared.u64 t, %1; cvt.u32.u64 %0, t; }" : "=r"(a) : "l"(p));
    return a;
}
#define LDSM4(r, a) \
    asm volatile("ldmatrix.sync.aligned.m8n8.x4.shared.b16 {%0,%1,%2,%3}, [%4];" \
        : "=r"((r)[0]), "=r"((r)[1]), "=r"((r)[2]), "=r"((r)[3]) : "r"(a))

__device__ __forceinline__ void mma16816(float* c, const uint32_t* a, const uint32_t* b) {
    asm volatile("mma.sync.aligned.m16n8k16.row.col.f32.bf16.bf16.f32 "
        "{%0,%1,%2,%3},{%4,%5,%6,%7},{%8,%9},{%0,%1,%2,%3};"
        : "+f"(c[0]), "+f"(c[1]), "+f"(c[2]), "+f"(c[3])
        : "r"(a[0]), "r"(a[1]), "r"(a[2]), "r"(a[3]), "r"(b[0]), "r"(b[1]));
}

__device__ __forceinline__ void split8(const float* v, uint4& h4, uint4& l4) {
    uint32_t h[4], l[4];
#pragma unroll
    for (int i = 0; i < 4; i++) {
        __nv_bfloat16 a = __float2bfloat16(v[2*i]), b = __float2bfloat16(v[2*i+1]);
        __nv_bfloat16 ra = __float2bfloat16(v[2*i]   - __bfloat162float(a));
        __nv_bfloat16 rb = __float2bfloat16(v[2*i+1] - __bfloat162float(b));
        h[i] = (uint32_t)__bfloat16_as_ushort(a)  | ((uint32_t)__bfloat16_as_ushort(b)  << 16);
        l[i] = (uint32_t)__bfloat16_as_ushort(ra) | ((uint32_t)__bfloat16_as_ushort(rb) << 16);
    }
    h4 = make_uint4(h[0], h[1], h[2], h[3]);
    l4 = make_uint4(l[0], l[1], l[2], l[3]);
}
__device__ __forceinline__ void plane_w8(__nv_bfloat16* img, int m, int k, const float* v) {
    uint4 h4, l4;
    split8(v, h4, l4);
    *(uint4*)(img + (size_t)m * 4096 + k) = h4;
    *(uint4*)(img + PLANE_A + (size_t)m * 4096 + k) = l4;
}

// ---------------- init (pre-loop launch #1) ----------------
__global__ __launch_bounds__(256) void init_k(
    const float* __restrict__ position, const float* __restrict__ momf,
    const float* __restrict__ momb, const float* __restrict__ b1,
    const float* __restrict__ Wt, const float* __restrict__ ts)
{
    int idx = blockIdx.x * 256 + threadIdx.x;
    if (idx < Bc * Dc) {
        float p = position[idx];
        g_posF[idx] = p; g_posB[idx] = p;
        g_momF[idx] = momf[idx]; g_momB[idx] = momb[idx];
    }
    if (idx < 2 * NSc * Hc) {
        int h = idx % Hc, s = (idx / Hc) % NSc, n = idx / (Hc * NSc);
        g_bias1[idx] = b1[n * Hc + h]
                     + ts[s * 2 + 0] * Wt[(n * 2 + 0) * Hc + h]
                     + ts[s * 2 + 1] * Wt[(n * 2 + 1) * Hc + h];
    }
    if (idx < Bc) { g_sldF[idx] = 0.f; g_sldB[idx] = 0.f; }
}

// pre-loop launch #2
__global__ __launch_bounds__(256) void initA_k(const float* __restrict__ position)
{
    int r = blockIdx.x, d0 = threadIdx.x * 8;
    const float* src = position + (size_t)(r & 63) * Dc + d0;
    float xa[8], xb[8];
#pragma unroll
    for (int c = 0; c < 8; c++) { float p = src[c]; xa[c] = p; xb[c] = sinf(p); }
    plane_w8(g_A1img, r, d0, xa);
    plane_w8(g_A1img, r, 2048 + d0, xb);
}

// ---------------- weight transpose + split (3 launches, net = blockIdx.z) ---
__global__ __launch_bounds__(256) void tw_k(
    const float* __restrict__ S0, const float* __restrict__ S1,
    const float* __restrict__ S2, int gtype, int NSRC, int NTOT,
    __nv_bfloat16* __restrict__ dstBase, size_t srcStride, size_t dstOff)
{
    __shared__ float sm[64 * 129];
    const int j = blockIdx.x, kb = blockIdx.y, tid = threadIdx.x;
    const int n = blockIdx.z;
    S0 += (size_t)n * srcStride;
    if (S1) S1 += (size_t)n * srcStride;
    if (S2) S2 += (size_t)n * srcStride;
    __nv_bfloat16* dst = dstBase + (size_t)n * NET_STRIDE + dstOff;

    int n0 = (gtype == 3) ? (j & 15) * 128 : j * 128;
#pragma unroll
    for (int p = 0; p < 8; p++) {
        int kk = p * 8 + (tid >> 5), nn = (tid & 31) * 4;
        int kg = kb * 64 + kk;
        const float* sp;
        if (gtype == 1)      sp = (kg < 2048) ? S0 + (size_t)kg * NSRC : S1 + (size_t)(kg - 2048) * NSRC;
        else if (gtype == 2) sp = S0 + (size_t)kg * NSRC;
        else { const float* W = (j < 16) ? S0 : ((j < 32) ? S1 : S2); sp = W + (size_t)kg * NSRC; }
        float4 vv = *(const float4*)(sp + n0 + nn);
        sm[kk * 129 + nn + 0] = vv.x; sm[kk * 129 + nn + 1] = vv.y;
        sm[kk * 129 + nn + 2] = vv.z; sm[kk * 129 + nn + 3] = vv.w;
    }
    __syncthreads();
    size_t planeStride = (size_t)NTOT * 4096;
    int nbase = j * 128;
#pragma unroll
    for (int p = 0; p < 4; p++) {
        int pi = tid + p * 256;
        int rr = pi >> 3, u = pi & 7;
        float v[8];
#pragma unroll
        for (int c = 0; c < 8; c++) v[c] = sm[(u * 8 + c) * 129 + rr];
        uint4 h4, l4;
        split8(v, h4, l4);
        size_t off = (size_t)(nbase + rr) * 4096 + kb * 64 + u * 8;
        *(uint4*)(dst + off) = h4;
        *(uint4*)(dst + planeStride + off) = l4;
    }
}

// ---------------- HMMA GEMM: C[128 x 128] tile, split-K over blockIdx.z -----
__device__ __forceinline__ void ld_chunk(char* sbase, int tid,
    const __nv_bfloat16* Ahi, const __nv_bfloat16* Alo,
    const __nv_bfloat16* Whi, const __nv_bfloat16* Wlo, int kb)
{
#pragma unroll
    for (int j = 0; j < 16; j++) {
        int v = j * 256 + tid;
        int p = v >> 10, w = v & 1023;
        int r = w >> 3, c = w & 7;
        const __nv_bfloat16* src =
            (p == 0) ? Ahi + (size_t)r * 4096 + kb + c * 8 :
            (p == 1) ? Alo + (size_t)r * 4096 + kb + c * 8 :
            (p == 2) ? Whi + (size_t)r * 4096 + kb + c * 8 :
                       Wlo + (size_t)r * 4096 + kb + c * 8;
        uint32_t dst = smem_u32(sbase + p * 16384 + r * 128 + ((c ^ (r & 7)) << 4));
        asm volatile("cp.async.cg.shared.global [%0], [%1], 16;" :: "r"(dst), "l"(src));
    }
    asm volatile("cp.async.commit_group;" ::: "memory");
}

// NCHB chunks per z, first z gets NCHB+EXTRA (covers uneven split-K).
__global__ __launch_bounds__(256) void mma_gemm_k(
    const __nv_bfloat16* __restrict__ Aimg, const __nv_bfloat16* __restrict__ W,
    float* __restrict__ Pout, int NTOT, int NCHB, int EXTRA)
{
    extern __shared__ __align__(16) char smem[];
    const int tid = threadIdx.x, wid = tid >> 5, lane = tid & 31;
    const int ntile = blockIdx.x, z = blockIdx.z;
    const int nch = NCHB + (z == 0 ? EXTRA : 0);
    const int kc0 = z * NCHB + (z > 0 ? EXTRA : 0);
    const int n0 = ntile * 128;
    const int wm = (wid >> 2) * 64;
    const int wn = (wid & 3) * 32;

    const __nv_bfloat16* Ahi = Aimg;
    const __nv_bfloat16* Alo = Aimg + PLANE_A;
    const __nv_bfloat16* Whi = W + (size_t)n0 * 4096;
    const __nv_bfloat16* Wlo = W + (size_t)NTOT * 4096 + (size_t)n0 * 4096;

    float acc[4][4][4];
#pragma unroll
    for (int f = 0; f < 4; f++)
#pragma unroll
        for (int g = 0; g < 4; g++)
#pragma unroll
            for (int q = 0; q < 4; q++) acc[f][g][q] = 0.f;

    // 3-stage pipeline: prefetch chunks 0 and 1
    ld_chunk(smem, tid, Ahi, Alo, Whi, Wlo, (kc0 + 0) * 64);
    ld_chunk(smem + 65536, tid, Ahi, Alo, Whi, Wlo, (kc0 + 1) * 64);

    const int sub = lane >> 3;
    const int arow = wm + (lane & 7) + ((sub & 1) ? 8 : 0);
    const int brow = wn + (lane & 7) + ((sub >> 1) ? 8 : 0);

    for (int i = 0; i < nch; i++) {
        if (i + 2 < nch) {
            ld_chunk(smem + ((i + 2) % 3) * 65536, tid, Ahi, Alo, Whi, Wlo,
                     (kc0 + i + 2) * 64);
            asm volatile("cp.async.wait_group 2;" ::: "memory");
        } else if (i + 1 < nch) {
            asm volatile("cp.async.wait_group 1;" ::: "memory");
        } else {
            asm volatile("cp.async.wait_group 0;" ::: "memory");
        }
        __syncthreads();

        char* sb = smem + (i % 3) * 65536;
        uint32_t sA = smem_u32(sb);
        uint32_t sB = sA + 32768;
#pragma unroll
        for (int ks = 0; ks < 4; ks++) {
            uint32_t ahi[4][4], alo[4][4], bhi[4][2], blo[4][2];
            int akc = ks * 2 + (sub >> 1);
            int bkc = ks * 2 + (sub & 1);
#pragma unroll
            for (int f = 0; f < 4; f++) {
                int row = arow + f * 16;
                uint32_t ad = sA + row * 128 + ((akc ^ (row & 7)) << 4);
                LDSM4(ahi[f], ad);
                LDSM4(alo[f], ad + 16384);
            }
#pragma unroll
            for (int g = 0; g < 2; g++) {
                int row = brow + g * 16;
                uint32_t bd = sB + row * 128 + ((bkc ^ (row & 7)) << 4);
                uint32_t t[4];
                LDSM4(t, bd);
                bhi[g*2][0] = t[0]; bhi[g*2][1] = t[1];
                bhi[g*2+1][0] = t[2]; bhi[g*2+1][1] = t[3];
                LDSM4(t, bd + 16384);
                blo[g*2][0] = t[0]; blo[g*2][1] = t[1];
                blo[g*2+1][0] = t[2]; blo[g*2+1][1] = t[3];
            }
#pragma unroll
            for (int f = 0; f < 4; f++)
#pragma unroll
                for (int g = 0; g < 4; g++) {
                    mma16816(acc[f][g], ahi[f], bhi[g]);
                    mma16816(acc[f][g], ahi[f], blo[g]);
                    mma16816(acc[f][g], alo[f], bhi[g]);
                }
        }
        __syncthreads();
    }

    float* P = Pout + (size_t)z * 128 * NTOT;
    int mrow = wm + (lane >> 2);
    int ncol0 = n0 + wn + (lane & 3) * 2;
#pragma unroll
    for (int f = 0; f < 4; f++)
#pragma unroll
        for (int g = 0; g < 4; g++) {
            size_t o0 = (size_t)(mrow + f * 16) * NTOT + ncol0 + g * 8;
            *(float2*)(P + o0) = make_float2(acc[f][g][0], acc[f][g][1]);
            *(float2*)(P + o0 + 8 * NTOT) = make_float2(acc[f][g][2], acc[f][g][3]);
        }
}

// ---------------- activation: sum 4 split-K partials + bias + relu ----------
__global__ __launch_bounds__(256) void act_k(
    const float* __restrict__ P,
    const float* __restrict__ biasF, const float* __restrict__ biasB,
    __nv_bfloat16* __restrict__ outImg)
{
    int idx = blockIdx.x * 256 + threadIdx.x;
    int m = idx >> 9, k0 = (idx & 511) * 8;
    const float* row = P + (size_t)m * 4096 + k0;
    float v[8];
#pragma unroll
    for (int h = 0; h < 2; h++) {
        float4 a0 = *(const float4*)(row + h * 4);
        float4 a1 = *(const float4*)(row + STR12 + h * 4);
        float4 a2 = *(const float4*)(row + 2 * STR12 + h * 4);
        float4 a3 = *(const float4*)(row + 3 * STR12 + h * 4);
        v[h*4+0] = a0.x + a1.x + a2.x + a3.x;
        v[h*4+1] = a0.y + a1.y + a2.y + a3.y;
        v[h*4+2] = a0.z + a1.z + a2.z + a3.z;
        v[h*4+3] = a0.w + a1.w + a2.w + a3.w;
    }
    const float* bias = (m < 64) ? biasF : biasB;
#pragma unroll
    for (int c = 0; c < 8; c++) v[c] = fmaxf(v[c] + bias[k0 + c], 0.f);
    plane_w8(outImg, m, k0, v);
}

// ---------------- leapfrog elementwise + next-input planes ----------------
__global__ __launch_bounds__(256) void ep_k(
    int type, const float* __restrict__ eps,
    const float* __restrict__ bs, const float* __restrict__ cs,
    const float* __restrict__ btr, const float* __restrict__ bq,
    const float* __restrict__ cq,
    const float* cmF, int ciF, const float* cmB, int ciB,
    int nextType, const float* nmF, int niF, const float* nmB, int niB)
{
    const int r = blockIdx.x;
    const bool fwd = (r < 64);
    const int sr = fwd ? r : r - 64;
    float* pos = fwd ? g_posF : g_posB;
    float* mom = fwd ? g_momF : g_momB;
    const float* cm = fwd ? cmF : cmB;  const int ci = fwd ? ciF : ciB;
    const float* nm = fwd ? nmF : nmB;  const int ni = fwd ? niF : niB;
    const float e = eps[0];
    const int d0 = threadIdx.x * 8;

    float xa[8], xb[8], lds = 0.f;
#pragma unroll
    for (int c = 0; c < 8; c++) {
        int d = d0 + c;
        size_t ro = (size_t)r * 6144 + d;
        size_t so = (size_t)sr * Dc + d;
        float s0 = g_P3[ro] + g_P3[SZ3 + ro] + g_P3[2 * SZ3 + ro];
        float t0 = g_P3[ro + 2048] + g_P3[SZ3 + ro + 2048] + g_P3[2 * SZ3 + ro + 2048];
        float q0 = g_P3[ro + 4096] + g_P3[SZ3 + ro + 4096] + g_P3[2 * SZ3 + ro + 4096];
        float Sv = tanhf(s0 + bs[d]) * expf(cs[d]);
        float Tv = t0 + btr[d];
        float Qv = tanhf(q0 + bq[d]) * expf(cq[d]);
        float etr = expf(e * Qv);
        float p = pos[so], v = mom[so];
        if (type == 1) {
            float gg = sinf(p);
            float sc = (fwd ? 0.5f : -0.5f) * e * Sv;
            float es = expf(sc);
            v = fwd ? (v * es - 0.5f * e * (etr * gg - Tv))
                    : (es * (v + 0.5f * e * (etr * gg - Tv)));
            mom[so] = v;
            lds += sc;
        } else {
            float mk = cm[d]; if (ci) mk = 1.f - mk;
            float mi = 1.f - mk;
            float sc = e * Sv;
            float es = expf(sc);
            p = fwd ? (mk * p + mi * (p * es + e * (etr * v + Tv)))
                    : (mk * p + mi * es * (p - e * (etr * v + Tv)));
            pos[so] = p;
            lds += mi * sc;
        }
        if (nextType == 1) { xa[c] = p; xb[c] = sinf(p); }
        else { float k = nm[d]; if (ni) k = 1.f - k; xa[c] = v; xb[c] = k * p; }
    }
    plane_w8(g_A1img, r, d0, xa);
    plane_w8(g_A1img, r, 2048 + d0, xb);

    __shared__ float red[256];
    red[threadIdx.x] = lds;
    __syncthreads();
    for (int s2 = 128; s2 > 0; s2 >>= 1) {
        if (threadIdx.x < s2) red[threadIdx.x] += red[threadIdx.x + s2];
        __syncthreads();
    }
    if (threadIdx.x == 0) { (fwd ? g_sldF : g_sldB)[sr] += red[0]; }
}

// ---------------- final assembly ----------------
__global__ __launch_bounds__(256) void final_k(
    const float* __restrict__ position, const float* __restrict__ momf0,
    const float* __restrict__ momb0, const float* __restrict__ u_dir,
    const float* __restrict__ u_accept, float* __restrict__ out)
{
    const int b = blockIdx.x;
    float a7[7] = {0,0,0,0,0,0,0};
    for (int d = threadIdx.x; d < Dc; d += 256) {
        size_t o = (size_t)b * Dc + d;
        float x0 = position[o];  a7[0] += 1.f - cosf(x0);
        float a  = momf0[o];     a7[1] += 0.5f * a * a;
        float c  = momb0[o];     a7[2] += 0.5f * c * c;
        float pf = g_posF[o];    a7[3] += 1.f - cosf(pf);
        float mf = g_momF[o];    a7[4] += 0.5f * mf * mf;
        float pb = g_posB[o];    a7[5] += 1.f - cosf(pb);
        float mb = g_momB[o];    a7[6] += 0.5f * mb * mb;
    }
    __shared__ float red[256];
    __shared__ float tot[7];
    for (int q = 0; q < 7; q++) {
        red[threadIdx.x] = a7[q];
        __syncthreads();
        for (int s2 = 128; s2 > 0; s2 >>= 1) {
            if (threadIdx.x < s2) red[threadIdx.x] += red[threadIdx.x + s2];
            __syncthreads();
        }
        if (threadIdx.x == 0) tot[q] = red[0];
        __syncthreads();
    }
    __shared__ float s_fm, s_am;
    if (threadIdx.x == 0) {
        float df  = (tot[0] + tot[1]) - (tot[3] + tot[4]) + g_sldF[b];
        float apf = expf(fminf(df, 0.f)); if (!isfinite(apf)) apf = 0.f;
        float db  = (tot[0] + tot[2]) - (tot[5] + tot[6]) + g_sldB[b];
        float apb = expf(fminf(db, 0.f)); if (!isfinite(apb)) apb = 0.f;
        float fm  = (u_dir[b] > 0.5f) ? 1.f : 0.f;
        float ap  = fm * apf + (1.f - fm) * apb;
        out[2 * Bc * Dc + b] = ap;
        s_fm = fm;
        s_am = (ap > u_accept[b]) ? 1.f : 0.f;
    }
    __syncthreads();
    const float fm = s_fm, am = s_am;
    for (int d = threadIdx.x; d < Dc; d += 256) {
        size_t o = (size_t)b * Dc + d;
        float pp = fm * g_posF[o] + (1.f - fm) * g_posB[o];
        float mp = fm * g_momF[o] + (1.f - fm) * g_momB[o];
        out[o] = pp;
        out[(size_t)Bc * Dc + o] = mp;
        out[(size_t)2 * Bc * Dc + Bc + o] = am * pp + (1.f - am) * position[o];
    }
}

// ---------------- host driver ----------------
extern "C" void kernel_launch(void* const* d_in, const int* in_sizes, int n_in,
                              void* d_out, int out_size)
{
    const float* position = (const float*)d_in[0];
    const float* momf     = (const float*)d_in[1];
    const float* momb     = (const float*)d_in[2];
    const float* u_dir    = (const float*)d_in[3];
    const float* u_acc    = (const float*)d_in[4];
    const float* eps      = (const float*)d_in[5];
    const float* masks    = (const float*)d_in[6];
    const float* ts       = (const float*)d_in[7];
    const float* W1       = (const float*)d_in[8];
    const float* W2       = (const float*)d_in[9];
    const float* Wt       = (const float*)d_in[10];
    const float* b1       = (const float*)d_in[11];
    const float* Wh       = (const float*)d_in[12];
    const float* bh       = (const float*)d_in[13];
    const float* Ws       = (const float*)d_in[14];
    const float* bs       = (const float*)d_in[15];
    const float* cs       = (const float*)d_in[16];
    const float* Wtr      = (const float*)d_in[17];
    const float* btr      = (const float*)d_in[18];
    const float* Wq       = (const float*)d_in[19];
    const float* bq       = (const float*)d_in[20];
    const float* cq       = (const float*)d_in[21];
    float* out = (float*)d_out;

    const int DSM = 3 * 65536;
    cudaFuncSetAttribute(mma_gemm_k, cudaFuncAttributeMaxDynamicSharedMemorySize, DSM);

    void *pW, *pA1, *pA2, *pA3, *pP1, *pP2, *pP3, *pBias;
    cudaGetSymbolAddress(&pW,  g_Wimg);
    cudaGetSymbolAddress(&pA1, g_A1img);
    cudaGetSymbolAddress(&pA2, g_A2img);
    cudaGetSymbolAddress(&pA3, g_A3img);
    cudaGetSymbolAddress(&pP1, g_P1);
    cudaGetSymbolAddress(&pP2, g_P2);
    cudaGetSymbolAddress(&pP3, g_P3);
    cudaGetSymbolAddress(&pBias, g_bias1);
    __nv_bfloat16* Wimg = (__nv_bfloat16*)pW;
    const float* bias1d = (const float*)pBias;

    // pre-loop: exactly 5 launches so ncu (-s 5 -c 1) captures GEMM1
    init_k<<<800, 256>>>(position, momf, momb, b1, Wt, ts);
    initA_k<<<128, 256>>>(position);
    tw_k<<<dim3(32, 64, 2), 256>>>(W1, W2, nullptr, 1, Hc, 4096,
                                   Wimg, (size_t)Dc * Hc, R1OFF);
    tw_k<<<dim3(32, 64, 2), 256>>>(Wh, nullptr, nullptr, 2, Hc, 4096,
                                   Wimg, (size_t)Hc * Hc, R2OFF);
    tw_k<<<dim3(48, 64, 2), 256>>>(Ws, Wtr, Wq, 3, Dc, 6144,
                                   Wimg, (size_t)Hc * Dc, R3OFF);

    for (int step = 0; step < NSc; step++) {
        const int sF = step, sB = NSc - 1 - step;
        const float* mF = masks + (size_t)sF * Dc;
        const float* mB = masks + (size_t)sB * Dc;

        for (int sub = 0; sub < 4; sub++) {
            const int n = (sub == 0 || sub == 3) ? 1 : 0;   // MOM=1, POS=0
            __nv_bfloat16* base = Wimg + (size_t)n * NET_STRIDE;

            mma_gemm_k<<<dim3(32, 1, 4), 256, DSM>>>(
                (const __nv_bfloat16*)pA1, base + R1OFF, (float*)pP1, 4096, 16, 0);
            act_k<<<256, 256>>>((const float*)pP1,
                                bias1d + ((size_t)n * NSc + sF) * Hc,
                                bias1d + ((size_t)n * NSc + sB) * Hc,
                                (__nv_bfloat16*)pA2);
            mma_gemm_k<<<dim3(32, 1, 4), 256, DSM>>>(
                (const __nv_bfloat16*)pA2, base + R2OFF, (float*)pP2, 4096, 16, 0);
            act_k<<<256, 256>>>((const float*)pP2,
                                bh + (size_t)n * Hc, bh + (size_t)n * Hc,
                                (__nv_bfloat16*)pA3);
            // GEMM3: 48 ntiles x 3 split-K = 144 CTAs (one clean wave);
            // K chunks 64 = 22 + 21 + 21
            mma_gemm_k<<<dim3(48, 1, 3), 256, DSM>>>(
                (const __nv_bfloat16*)pA3, base + R3OFF, (float*)pP3, 6144, 21, 1);

            int type, nextType;
            const float *cmF = nullptr, *cmB = nullptr, *nmF = nullptr, *nmB = nullptr;
            int ciF = 0, ciB = 0, niF = 0, niB = 0;
            if (sub == 0) {
                type = 1; nextType = 0; nmF = mF; niF = 0; nmB = mB; niB = 1;
            } else if (sub == 1) {
                type = 0; nextType = 0;
                cmF = mF; ciF = 0; cmB = mB; ciB = 1;
                nmF = mF; niF = 1; nmB = mB; niB = 0;
            } else if (sub == 2) {
                type = 0; nextType = 1; cmF = mF; ciF = 1; cmB = mB; ciB = 0;
            } else {
                type = 1; nextType = 1;
            }
            ep_k<<<128, 256>>>(type, eps,
                               bs + (size_t)n * Dc, cs + (size_t)n * Dc,
                               btr + (size_t)n * Dc, bq + (size_t)n * Dc,
                               cq + (size_t)n * Dc,
                               cmF, ciF, cmB, ciB,
                               nextType, nmF, niF, nmB, niB);
        }
    }

    final_k<<<64, 256>>>(position, momf, momb, u_dir, u_acc, out);
}